// round 3
// baseline (speedup 1.0000x reference)
#include <cuda_runtime.h>
#include <cuda_bf16.h>

#define E_MAX   250000
#define A_MAX   10000
#define CHUNK   128     // edges staged per barrier round

// Scratch (no allocations allowed -> __device__ globals)
__device__ int g_count[A_MAX];
__device__ int g_offsets[A_MAX];
__device__ int g_cursor[A_MAX];
__device__ int g_edge_order[E_MAX];

// ---------------------------------------------------------------------------
__global__ void reset_kernel(int nAtoms) {
    int i = blockIdx.x * blockDim.x + threadIdx.x;
    if (i < nAtoms) g_count[i] = 0;
}

__global__ void count_kernel(const int* __restrict__ centers, int E) {
    int e = blockIdx.x * blockDim.x + threadIdx.x;
    if (e < E) atomicAdd(&g_count[centers[e]], 1);
}

__global__ void scan_kernel(int nAtoms) {
    __shared__ int part[1024];
    const int tid = threadIdx.x;
    const int chunk = (nAtoms + 1023) >> 10;
    const int b = tid * chunk;
    const int e = min(b + chunk, nAtoms);

    int s = 0;
    for (int i = b; i < e; i++) s += g_count[i];
    part[tid] = s;
    __syncthreads();
    for (int off = 1; off < 1024; off <<= 1) {
        int t = 0;
        if (tid >= off) t = part[tid - off];
        __syncthreads();
        part[tid] += t;
        __syncthreads();
    }
    int run = part[tid] - s;
    for (int i = b; i < e; i++) {
        g_offsets[i] = run;
        g_cursor[i]  = run;
        run += g_count[i];
    }
}

__global__ void scatter_kernel(const int* __restrict__ centers, int E) {
    int e = blockIdx.x * blockDim.x + threadIdx.x;
    if (e < E) {
        int c = centers[e];
        int p = atomicAdd(&g_cursor[c], 1);
        g_edge_order[p] = e;
    }
}

// ---------------------------------------------------------------------------
// k-slice worker: this thread owns 2 consecutive k-channels of one l and
// accumulates ALL (2l+1) m values for them. rb is read exactly once per edge
// across the CTA; sh comes from SMEM (staged per chunk, broadcast LDS).
template<int MC, int KL, int SHB>
__device__ __forceinline__ void run_region(
    const int tid, const int k,
    const float* __restrict__ rb,   const float* __restrict__ emb,
    const int*   __restrict__ neighbors,
    const float* __restrict__ sh0, const float* __restrict__ sh1,
    const float* __restrict__ sh2, const float* __restrict__ sh3,
    const int*   __restrict__ el,  const int cnt,
    float* __restrict__ outp,
    int* s_e, int* s_nbr, float (*s_sh)[16])
{
    float2 acc[MC];
    #pragma unroll
    for (int m = 0; m < MC; m++) { acc[m].x = 0.f; acc[m].y = 0.f; }

    const float2* __restrict__ emb2 = (const float2*)emb;

    for (int base = 0; base < cnt; base += CHUNK) {
        const int n = min(CHUNK, cnt - base);

        // Stage edge ids, neighbor ids, and all 16 sh values per edge.
        for (int idx = tid; idx < n * 16; idx += 320) {
            const int i = idx >> 4;
            const int c = idx & 15;
            const int e = el[base + i];
            float v;
            if (c == 0)      { s_e[i] = e; s_nbr[i] = neighbors[e]; v = sh0[e]; }
            else if (c < 4)  v = sh1[(long)e * 3 + (c - 1)];
            else if (c < 9)  v = sh2[(long)e * 5 + (c - 4)];
            else             v = sh3[(long)e * 7 + (c - 9)];
            s_sh[i][c] = v;
        }
        __syncthreads();

        #pragma unroll 4
        for (int i = 0; i < n; i++) {
            const int e   = s_e[i];
            const int nbr = s_nbr[i];
            const float2 a = *(const float2*)(rb + (long)e * KL + k);
            const float2 b = emb2[nbr * 128 + (k >> 1)];
            const float px = a.x * b.x;
            const float py = a.y * b.y;
            #pragma unroll
            for (int m = 0; m < MC; m++) {
                const float s = s_sh[i][SHB + m];
                acc[m].x += s * px;
                acc[m].y += s * py;
            }
        }
        __syncthreads();
    }

    #pragma unroll
    for (int m = 0; m < MC; m++)
        *(float2*)(outp + (long)m * KL) = acc[m];
}

// One CTA per atom, 320 threads. Warp-uniform l regions:
//   warps 0-3 (t 0-127):   l0, k = 2t          (256 ch)
//   warps 4-6 (t 128-223): l1, k = 2(t-128)    (192 ch)
//   warps 7-8 (t 224-287): l2, k = 2(t-224)    (128 ch)
//   warp  9   (t 288-319): l3, k = 2(t-288)    (64 ch)
__global__ void __launch_bounds__(320)
density_kernel(const float* __restrict__ sh0, const float* __restrict__ sh1,
               const float* __restrict__ sh2, const float* __restrict__ sh3,
               const float* __restrict__ rb0, const float* __restrict__ rb1,
               const float* __restrict__ rb2, const float* __restrict__ rb3,
               const float* __restrict__ emb, const int* __restrict__ neighbors,
               float* __restrict__ out, int nAtoms)
{
    const int atom = blockIdx.x;
    const int tid  = threadIdx.x;

    __shared__ int   s_e[CHUNK];
    __shared__ int   s_nbr[CHUNK];
    __shared__ float s_sh[CHUNK][16];

    const long B1 = (long)nAtoms * 256;
    const long B2 = B1 + (long)nAtoms * 576;
    const long B3 = B2 + (long)nAtoms * 640;

    const int  start = g_offsets[atom];
    const int  cnt   = g_count[atom];
    const int* el    = g_edge_order + start;

    if (tid < 128) {
        const int k = tid * 2;
        run_region<1, 256, 0>(tid, k, rb0, emb, neighbors, sh0, sh1, sh2, sh3,
                              el, cnt, out + (long)atom * 256 + k,
                              s_e, s_nbr, s_sh);
    } else if (tid < 224) {
        const int k = (tid - 128) * 2;
        run_region<3, 192, 1>(tid, k, rb1, emb, neighbors, sh0, sh1, sh2, sh3,
                              el, cnt, out + B1 + (long)atom * 576 + k,
                              s_e, s_nbr, s_sh);
    } else if (tid < 288) {
        const int k = (tid - 224) * 2;
        run_region<5, 128, 4>(tid, k, rb2, emb, neighbors, sh0, sh1, sh2, sh3,
                              el, cnt, out + B2 + (long)atom * 640 + k,
                              s_e, s_nbr, s_sh);
    } else {
        const int k = (tid - 288) * 2;
        run_region<7, 64, 9>(tid, k, rb3, emb, neighbors, sh0, sh1, sh2, sh3,
                              el, cnt, out + B3 + (long)atom * 448 + k,
                              s_e, s_nbr, s_sh);
    }
}

// ---------------------------------------------------------------------------
extern "C" void kernel_launch(void* const* d_in, const int* in_sizes, int n_in,
                              void* d_out, int out_size)
{
    const float* sh[4];
    const float* rb[4];
    const bool interleaved = ((long)in_sizes[1] > (long)in_sizes[0] * 8);
    for (int l = 0; l < 4; l++) {
        if (interleaved) {
            sh[l] = (const float*)d_in[2 * l];
            rb[l] = (const float*)d_in[2 * l + 1];
        } else {
            sh[l] = (const float*)d_in[l];
            rb[l] = (const float*)d_in[4 + l];
        }
    }
    const float* emb       = (const float*)d_in[8];
    const int*   centers   = (const int*)d_in[9];
    const int*   neighbors = (const int*)d_in[10];
    float*       out       = (float*)d_out;

    const int E      = in_sizes[9];
    const int nAtoms = in_sizes[8] / 256;

    const int TB = 256;
    reset_kernel  <<<(nAtoms + TB - 1) / TB, TB>>>(nAtoms);
    count_kernel  <<<(E + TB - 1) / TB, TB>>>(centers, E);
    scan_kernel   <<<1, 1024>>>(nAtoms);
    scatter_kernel<<<(E + TB - 1) / TB, TB>>>(centers, E);
    density_kernel<<<nAtoms, 320>>>(sh[0], sh[1], sh[2], sh[3],
                                    rb[0], rb[1], rb[2], rb[3],
                                    emb, neighbors, out, nAtoms);
}

// round 4
// speedup vs baseline: 1.1561x; 1.1561x over previous
#include <cuda_runtime.h>
#include <cuda_bf16.h>

#define E_MAX   250000
#define A_MAX   10000
#define CHUNK   128     // edges staged per barrier round

// Scratch (no allocations allowed -> __device__ globals).
// g_count is zero-initialized at module load; scan_kernel re-zeros it after
// consuming it, so every call's count_kernel starts from zero.
__device__ int g_count[A_MAX];
__device__ int g_offsets[A_MAX + 1];
__device__ int g_cursor[A_MAX];
__device__ int g_edge_order[E_MAX];

// ---------------------------------------------------------------------------
__global__ void count_kernel(const int* __restrict__ centers, int E) {
    int e = blockIdx.x * blockDim.x + threadIdx.x;
    if (e < E) atomicAdd(&g_count[centers[e]], 1);
}

// Single-block exclusive scan over nAtoms counts; also writes cursors,
// the E sentinel, and RE-ZEROS g_count for the next call.
__global__ void scan_kernel(int nAtoms, int E) {
    __shared__ int part[1024];
    const int tid = threadIdx.x;
    const int chunk = (nAtoms + 1023) >> 10;   // 10 for nAtoms=10000
    const int b = tid * chunk;
    const int e = min(b + chunk, nAtoms);

    int cnt[32];                                // chunk <= 32 assumed
    int s = 0;
    for (int i = b; i < e; i++) { cnt[i - b] = g_count[i]; s += cnt[i - b]; }
    part[tid] = s;
    __syncthreads();

    for (int off = 1; off < 1024; off <<= 1) {
        int t = 0;
        if (tid >= off) t = part[tid - off];
        __syncthreads();
        part[tid] += t;
        __syncthreads();
    }
    int run = part[tid] - s;
    for (int i = b; i < e; i++) {
        g_offsets[i] = run;
        g_cursor[i]  = run;
        run += cnt[i - b];
        g_count[i] = 0;                         // reset for next call
    }
    if (tid == 1023) g_offsets[nAtoms] = E;
}

__global__ void scatter_kernel(const int* __restrict__ centers, int E) {
    int e = blockIdx.x * blockDim.x + threadIdx.x;
    if (e < E) {
        int c = centers[e];
        int p = atomicAdd(&g_cursor[c], 1);
        g_edge_order[p] = e;
    }
}

// ---------------------------------------------------------------------------
// Density kernel: TWO CTAs per atom (blockIdx.x = atom*2 + half), 128 threads
// each, 120 active. Thread owns 8 consecutive flat channels of the 1920-wide
// output; all l/m/k boundaries are multiples of 8 so a chunk never straddles
// one. Inner loop is barrier-free and branch-uniform (per-thread pointers).
// Small CTAs + unroll 2 keep regs low -> many resident CTAs -> many
// independent edge streams to hide the random rb/emb gather latency.
__global__ void __launch_bounds__(128)
density_kernel(const float* __restrict__ sh0, const float* __restrict__ sh1,
               const float* __restrict__ sh2, const float* __restrict__ sh3,
               const float* __restrict__ rb0, const float* __restrict__ rb1,
               const float* __restrict__ rb2, const float* __restrict__ rb3,
               const float* __restrict__ emb, const int* __restrict__ neighbors,
               float* __restrict__ out, int nAtoms)
{
    const int atom = blockIdx.x >> 1;
    const int half = blockIdx.x & 1;
    const int tid  = threadIdx.x;

    __shared__ int s_e[CHUNK];
    __shared__ int s_nbr[CHUNK];

    const long B1 = (long)nAtoms * 256;
    const long B2 = B1 + (long)nAtoms * 576;
    const long B3 = B2 + (long)nAtoms * 640;

    const bool active = (tid < 120);

    const float* shp = sh0;
    int shstride = 1, shoff = 0;
    const float4* rbp = (const float4*)rb0;
    int rbstride4 = 64;
    int kq = 0;
    long obase = 0;

    if (active) {
        const int f = (half * 120 + tid) * 8;
        if (f < 256) {
            int k = f;
            shp = sh0; shstride = 1; shoff = 0;
            rbp = (const float4*)rb0; rbstride4 = 64; kq = k >> 2;
            obase = (long)atom * 256 + k;
        } else if (f < 832) {
            int r = f - 256; int m = r / 192; int k = r - 192 * m;
            shp = sh1; shstride = 3; shoff = m;
            rbp = (const float4*)rb1; rbstride4 = 48; kq = k >> 2;
            obase = B1 + (long)atom * 576 + (long)m * 192 + k;
        } else if (f < 1472) {
            int r = f - 832; int m = r >> 7; int k = r & 127;
            shp = sh2; shstride = 5; shoff = m;
            rbp = (const float4*)rb2; rbstride4 = 32; kq = k >> 2;
            obase = B2 + (long)atom * 640 + (long)m * 128 + k;
        } else {
            int r = f - 1472; int m = r >> 6; int k = r & 63;
            shp = sh3; shstride = 7; shoff = m;
            rbp = (const float4*)rb3; rbstride4 = 16; kq = k >> 2;
            obase = B3 + (long)atom * 448 + (long)m * 64 + k;
        }
    }

    float acc0 = 0.f, acc1 = 0.f, acc2 = 0.f, acc3 = 0.f;
    float acc4 = 0.f, acc5 = 0.f, acc6 = 0.f, acc7 = 0.f;

    const int start = g_offsets[atom];
    const int cnt   = g_offsets[atom + 1] - start;
    const float4* __restrict__ emb4 = (const float4*)emb;

    for (int base = 0; base < cnt; base += CHUNK) {
        const int n = min(CHUNK, cnt - base);
        for (int i = tid; i < n; i += 128) {
            int e = g_edge_order[start + base + i];
            s_e[i]   = e;
            s_nbr[i] = neighbors[e];
        }
        __syncthreads();

        if (active) {
            #pragma unroll 2
            for (int i = 0; i < n; i++) {
                const int  e   = s_e[i];
                const int  nbr = s_nbr[i];
                const float s  = __ldg(shp + (long)e * shstride + shoff);
                const float4 a0 = rbp[(long)e * rbstride4 + kq];
                const float4 a1 = rbp[(long)e * rbstride4 + kq + 1];
                const float4 b0 = emb4[(long)nbr * 64 + kq];
                const float4 b1 = emb4[(long)nbr * 64 + kq + 1];
                acc0 += s * (a0.x * b0.x);
                acc1 += s * (a0.y * b0.y);
                acc2 += s * (a0.z * b0.z);
                acc3 += s * (a0.w * b0.w);
                acc4 += s * (a1.x * b1.x);
                acc5 += s * (a1.y * b1.y);
                acc6 += s * (a1.z * b1.z);
                acc7 += s * (a1.w * b1.w);
            }
        }
        __syncthreads();
    }

    if (active) {
        float4* o = (float4*)(out + obase);
        o[0] = make_float4(acc0, acc1, acc2, acc3);
        o[1] = make_float4(acc4, acc5, acc6, acc7);
    }
}

// ---------------------------------------------------------------------------
extern "C" void kernel_launch(void* const* d_in, const int* in_sizes, int n_in,
                              void* d_out, int out_size)
{
    const float* sh[4];
    const float* rb[4];
    const bool interleaved = ((long)in_sizes[1] > (long)in_sizes[0] * 8);
    for (int l = 0; l < 4; l++) {
        if (interleaved) {
            sh[l] = (const float*)d_in[2 * l];
            rb[l] = (const float*)d_in[2 * l + 1];
        } else {
            sh[l] = (const float*)d_in[l];
            rb[l] = (const float*)d_in[4 + l];
        }
    }
    const float* emb       = (const float*)d_in[8];
    const int*   centers   = (const int*)d_in[9];
    const int*   neighbors = (const int*)d_in[10];
    float*       out       = (float*)d_out;

    const int E      = in_sizes[9];
    const int nAtoms = in_sizes[8] / 256;

    const int TB = 256;
    count_kernel  <<<(E + TB - 1) / TB, TB>>>(centers, E);
    scan_kernel   <<<1, 1024>>>(nAtoms, E);
    scatter_kernel<<<(E + TB - 1) / TB, TB>>>(centers, E);
    density_kernel<<<nAtoms * 2, 128>>>(sh[0], sh[1], sh[2], sh[3],
                                        rb[0], rb[1], rb[2], rb[3],
                                        emb, neighbors, out, nAtoms);
}

// round 5
// speedup vs baseline: 1.3491x; 1.1669x over previous
#include <cuda_runtime.h>
#include <cuda_bf16.h>

#define E_MAX   250000
#define A_MAX   10000
#define CHUNK   128     // edges staged per barrier round

// Scratch (no allocations allowed -> __device__ globals).
__device__ int g_count[A_MAX];
__device__ int g_offsets[A_MAX + 1];
__device__ int g_cursor[A_MAX];
__device__ int g_edge_order[E_MAX];

// ---------------------------------------------------------------------------
__global__ void count_kernel(const int* __restrict__ centers, int E) {
    int e = blockIdx.x * blockDim.x + threadIdx.x;
    if (e < E) atomicAdd(&g_count[centers[e]], 1);
}

// Single-block exclusive scan; writes cursors + sentinel, re-zeros g_count.
__global__ void scan_kernel(int nAtoms, int E) {
    __shared__ int part[1024];
    const int tid = threadIdx.x;
    const int chunk = (nAtoms + 1023) >> 10;
    const int b = tid * chunk;
    const int e = min(b + chunk, nAtoms);

    int cnt[32];
    int s = 0;
    for (int i = b; i < e; i++) { cnt[i - b] = g_count[i]; s += cnt[i - b]; }
    part[tid] = s;
    __syncthreads();
    for (int off = 1; off < 1024; off <<= 1) {
        int t = 0;
        if (tid >= off) t = part[tid - off];
        __syncthreads();
        part[tid] += t;
        __syncthreads();
    }
    int run = part[tid] - s;
    for (int i = b; i < e; i++) {
        g_offsets[i] = run;
        g_cursor[i]  = run;
        run += cnt[i - b];
        g_count[i] = 0;
    }
    if (tid == 1023) g_offsets[nAtoms] = E;
}

__global__ void scatter_kernel(const int* __restrict__ centers, int E) {
    int e = blockIdx.x * blockDim.x + threadIdx.x;
    if (e < E) {
        int c = centers[e];
        int p = atomicAdd(&g_cursor[c], 1);
        g_edge_order[p] = e;
    }
}

// ---------------------------------------------------------------------------
// s_sh layout per edge: 16 contiguous floats = 4 quads:
//   q0 = [sh0, sh1_0, sh1_1, sh1_2]
//   q1 = [sh2_0, sh2_1, sh2_2, sh2_3]
//   q2 = [sh2_4, sh3_0, sh3_1, sh3_2]
//   q3 = [sh3_3, sh3_4, sh3_5, sh3_6]
// Each warp pulls its sh values with <=2 broadcast LDS.128.

template<int L, int KL>
__device__ __forceinline__ void run_region(
    const int k,
    const float* __restrict__ rb, const float* __restrict__ emb,
    const int cnt, const int* __restrict__ el,
    const int* __restrict__ neighbors,
    const float* __restrict__ sh0, const float* __restrict__ sh1,
    const float* __restrict__ sh2, const float* __restrict__ sh3,
    float* __restrict__ outp,
    const int tid, int2* s_meta, float4* s_shq)
{
    constexpr int MC = 2 * L + 1;
    float2 acc[MC];
    #pragma unroll
    for (int m = 0; m < MC; m++) { acc[m].x = 0.f; acc[m].y = 0.f; }

    float* s_shf = (float*)s_shq;

    for (int base = 0; base < cnt; base += CHUNK) {
        const int n = min(CHUNK, cnt - base);

        // Stage meta + 16 sh floats per edge (coalesced-ish, amortized).
        for (int idx = tid; idx < n * 16; idx += 320) {
            const int i = idx >> 4;
            const int c = idx & 15;
            const int e = el[base + i];
            float v;
            if (c == 0)      { v = sh0[e]; s_meta[i] = make_int2(e, neighbors[e]); }
            else if (c < 4)  v = sh1[(long)e * 3 + (c - 1)];
            else if (c < 9)  v = sh2[(long)e * 5 + (c - 4)];
            else             v = sh3[(long)e * 7 + (c - 9)];
            s_shf[idx] = v;
        }
        __syncthreads();

        #pragma unroll 2
        for (int i = 0; i < n; i++) {
            const int2 me = s_meta[i];
            const float2 a = *(const float2*)(rb  + (long)me.x * KL  + k);
            const float2 b = *(const float2*)(emb + (long)me.y * 256 + k);
            const float px = a.x * b.x;
            const float py = a.y * b.y;

            float sh[MC];
            if (L == 0) {
                sh[0] = s_shf[i * 16];
            } else if (L == 1) {
                const float4 q0 = s_shq[i * 4];
                sh[0] = q0.y; if (MC > 1) sh[1] = q0.z; if (MC > 2) sh[2] = q0.w;
            } else if (L == 2) {
                const float4 q1 = s_shq[i * 4 + 1];
                const float4 q2 = s_shq[i * 4 + 2];
                sh[0] = q1.x; sh[1] = q1.y; sh[2] = q1.z; sh[3] = q1.w;
                sh[4] = q2.x;
            } else {
                const float4 q2 = s_shq[i * 4 + 2];
                const float4 q3 = s_shq[i * 4 + 3];
                sh[0] = q2.y; sh[1] = q2.z; sh[2] = q2.w;
                sh[3] = q3.x; sh[4] = q3.y; sh[5] = q3.z; sh[6] = q3.w;
            }

            #pragma unroll
            for (int m = 0; m < MC; m++) {
                acc[m].x += sh[m] * px;
                acc[m].y += sh[m] * py;
            }
        }
        __syncthreads();
    }

    #pragma unroll
    for (int m = 0; m < MC; m++)
        *(float2*)(outp + (long)m * KL) = acc[m];
}

// One CTA per atom, 320 threads, warp-aligned l regions:
//   t 0-127:   l0 (4 warps), k = 2t
//   t 128-223: l1 (3 warps), k = 2(t-128)
//   t 224-287: l2 (2 warps), k = 2(t-224)
//   t 288-319: l3 (1 warp),  k = 2(t-288)
__global__ void __launch_bounds__(320)
density_kernel(const float* __restrict__ sh0, const float* __restrict__ sh1,
               const float* __restrict__ sh2, const float* __restrict__ sh3,
               const float* __restrict__ rb0, const float* __restrict__ rb1,
               const float* __restrict__ rb2, const float* __restrict__ rb3,
               const float* __restrict__ emb, const int* __restrict__ neighbors,
               float* __restrict__ out, int nAtoms)
{
    const int atom = blockIdx.x;
    const int tid  = threadIdx.x;

    __shared__ int2   s_meta[CHUNK];
    __shared__ float4 s_shq[CHUNK * 4];

    const long B1 = (long)nAtoms * 256;
    const long B2 = B1 + (long)nAtoms * 576;
    const long B3 = B2 + (long)nAtoms * 640;

    const int  start = g_offsets[atom];
    const int  cnt   = g_offsets[atom + 1] - start;
    const int* el    = g_edge_order + start;

    if (tid < 128) {
        const int k = tid * 2;
        run_region<0, 256>(k, rb0, emb, cnt, el, neighbors, sh0, sh1, sh2, sh3,
                           out + (long)atom * 256 + k, tid, s_meta, s_shq);
    } else if (tid < 224) {
        const int k = (tid - 128) * 2;
        run_region<1, 192>(k, rb1, emb, cnt, el, neighbors, sh0, sh1, sh2, sh3,
                           out + B1 + (long)atom * 576 + k, tid, s_meta, s_shq);
    } else if (tid < 288) {
        const int k = (tid - 224) * 2;
        run_region<2, 128>(k, rb2, emb, cnt, el, neighbors, sh0, sh1, sh2, sh3,
                           out + B2 + (long)atom * 640 + k, tid, s_meta, s_shq);
    } else {
        const int k = (tid - 288) * 2;
        run_region<3, 64>(k, rb3, emb, cnt, el, neighbors, sh0, sh1, sh2, sh3,
                           out + B3 + (long)atom * 448 + k, tid, s_meta, s_shq);
    }
}

// ---------------------------------------------------------------------------
extern "C" void kernel_launch(void* const* d_in, const int* in_sizes, int n_in,
                              void* d_out, int out_size)
{
    const float* sh[4];
    const float* rb[4];
    const bool interleaved = ((long)in_sizes[1] > (long)in_sizes[0] * 8);
    for (int l = 0; l < 4; l++) {
        if (interleaved) {
            sh[l] = (const float*)d_in[2 * l];
            rb[l] = (const float*)d_in[2 * l + 1];
        } else {
            sh[l] = (const float*)d_in[l];
            rb[l] = (const float*)d_in[4 + l];
        }
    }
    const float* emb       = (const float*)d_in[8];
    const int*   centers   = (const int*)d_in[9];
    const int*   neighbors = (const int*)d_in[10];
    float*       out       = (float*)d_out;

    const int E      = in_sizes[9];
    const int nAtoms = in_sizes[8] / 256;

    const int TB = 256;
    count_kernel  <<<(E + TB - 1) / TB, TB>>>(centers, E);
    scan_kernel   <<<1, 1024>>>(nAtoms, E);
    scatter_kernel<<<(E + TB - 1) / TB, TB>>>(centers, E);
    density_kernel<<<nAtoms, 320>>>(sh[0], sh[1], sh[2], sh[3],
                                    rb[0], rb[1], rb[2], rb[3],
                                    emb, neighbors, out, nAtoms);
}